// round 5
// baseline (speedup 1.0000x reference)
#include <cuda_runtime.h>
#include <math.h>

#define BATCH 256
#define TLEN  50
#define NOBS  8192
#define NKC   50

// ---- device-global scratch (no allocations allowed) ----
__device__ unsigned char g_assign[NOBS];                 // assign[] as uint8
__device__ float         g_probs_scratch[BATCH * TLEN];  // fallback sink

// ============================================================
// k1: recover assign[] from one-hot A. Two independent float4
// loads per thread (MLP=2), 200 blocks x 256.
// ============================================================
__global__ __launch_bounds__(256)
void k1_prep(const float4* __restrict__ A4) {
    const int half = NOBS * NKC / 8;              // 51200 float4s per half
    int idx = blockIdx.x * 256 + threadIdx.x;
    float4 v0 = A4[idx];
    float4 v1 = A4[idx + half];

    int b0 = idx * 4;
    if (v0.x > 0.5f) { int i = b0 + 0; g_assign[i / NKC] = (unsigned char)(i % NKC); }
    if (v0.y > 0.5f) { int i = b0 + 1; g_assign[i / NKC] = (unsigned char)(i % NKC); }
    if (v0.z > 0.5f) { int i = b0 + 2; g_assign[i / NKC] = (unsigned char)(i % NKC); }
    if (v0.w > 0.5f) { int i = b0 + 3; g_assign[i / NKC] = (unsigned char)(i % NKC); }

    int b1 = (idx + half) * 4;
    if (v1.x > 0.5f) { int i = b1 + 0; g_assign[i / NKC] = (unsigned char)(i % NKC); }
    if (v1.y > 0.5f) { int i = b1 + 1; g_assign[i / NKC] = (unsigned char)(i % NKC); }
    if (v1.z > 0.5f) { int i = b1 + 2; g_assign[i / NKC] = (unsigned char)(i % NKC); }
    if (v1.w > 0.5f) { int i = b1 + 3; g_assign[i / NKC] = (unsigned char)(i % NKC); }
}

// ============================================================
// k2: fused recurrence + expansion, one block per batch row.
// Recurrence runs in WARP 0 with the compact state held in
// registers across lanes (lane l owns state[l] and state[l+32]);
// per-step state read = shfl (26 cyc), update = predicated
// register write. No STS->LDS hop on the carried chain.
// ============================================================
__global__ __launch_bounds__(128, 8)
void k2_fused(const int*   __restrict__ prev_kc,
              const int*   __restrict__ curr_kc,
              const float* __restrict__ prev_corr,
              const float* __restrict__ kc_logits,
              float*       __restrict__ probs_out,
              float*       __restrict__ state_out,
              int do_state) {
    __shared__ unsigned char s_assign[NOBS];   // 8 KB
    __shared__ float4        s_pr[NKC];        // sigmoid(pl,pf,p2,p3)
    __shared__ float         s_state[NKC];     // compact state (init / final)
    __shared__ unsigned char s_apk[TLEN];      // assign[pk] | corr<<7
    __shared__ unsigned char s_ack[TLEN];      // assign[ck]

    const int b   = blockIdx.x;
    const int tid = threadIdx.x;

    // --- copy g_assign -> shared (L2-hot, coalesced int4) ---
    {
        const int4* src = (const int4*)g_assign;
        int4*       dst = (int4*)s_assign;
        #pragma unroll
        for (int i = 0; i < 4; i++) dst[tid + 128 * i] = src[tid + 128 * i];
    }

    // --- row inputs + sigmoids (threads 0..49), overlap the copy ---
    int   pk = 0, ck = 0;
    float cr = 0.0f;
    if (tid < TLEN) {
        pk = prev_kc[b * TLEN + tid];
        ck = curr_kc[b * TLEN + tid];
        cr = prev_corr[b * TLEN + tid];

        float4 p;
        p.x = 1.0f / (1.0f + __expf(-kc_logits[tid * 5 + 0]));
        p.y = 1.0f / (1.0f + __expf(-kc_logits[tid * 5 + 1]));
        p.z = 1.0f / (1.0f + __expf(-kc_logits[tid * 5 + 2]));
        p.w = 1.0f / (1.0f + __expf(-kc_logits[tid * 5 + 3]));
        s_pr[tid]    = p;
        s_state[tid] = 1.0f / (1.0f + __expf(-kc_logits[tid * 5 + 4]));
    }
    __syncthreads();   // s_assign + s_pr/s_state complete

    if (tid < TLEN) {
        s_apk[tid] = s_assign[pk] | (cr > 0.5f ? (unsigned char)0x80 : (unsigned char)0);
        s_ack[tid] = s_assign[ck];
    }
    __syncthreads();

    // --- recurrence: warp 0, state in registers ---
    if (tid < 32) {
        const int lane = tid;
        float st0 = s_state[lane];                                   // KC lane
        float st1 = (lane < NKC - 32) ? s_state[lane + 32] : 0.0f;   // KC lane+32

        float* out = probs_out + b * TLEN;

        // t = 0: prediction only
        {
            int    ac = s_ack[0];
            float  a0 = __shfl_sync(0xffffffffu, st0, ac & 31);
            float  a1 = __shfl_sync(0xffffffffu, st1, ac & 31);
            float  cs = (ac < 32) ? a0 : a1;
            float4 pc = s_pr[ac];
            if (lane == 0) out[0] = fmaf(pc.w - pc.z, cs, pc.z);
        }

        #pragma unroll
        for (int t = 1; t < TLEN; t++) {
            unsigned int af = s_apk[t];
            int    ap = (int)(af & 0x7fu);
            float4 pp = s_pr[ap];

            // off-chain per-step constants
            float o0, o1;
            if (af & 0x80u) { o0 = pp.z;        o1 = pp.w;        }
            else            { o0 = 1.0f - pp.z; o1 = 1.0f - pp.w; }
            float d10 = o1 - o0;
            float c1  = 1.0f - pp.y - pp.x;

            // carried chain: shfl -> fma -> rcp -> mul -> fma -> sel
            float s0 = __shfl_sync(0xffffffffu, st0, ap & 31);
            float s1 = __shfl_sync(0xffffffffu, st1, ap & 31);
            float ss = (ap < 32) ? s0 : s1;

            float num  = o1 * ss;
            float den  = fmaf(d10, ss, o0);
            float filt = __fdividef(num, den);
            float pred = fmaf(c1, filt, pp.x);          // pl*(1-f)+(1-pf)*f

            if (lane == ap)      st0 = pred;
            if (lane == ap - 32) st1 = pred;            // no match when ap<32

            // output (off the carried chain)
            int    ac = s_ack[t];
            float  a0 = __shfl_sync(0xffffffffu, st0, ac & 31);
            float  a1 = __shfl_sync(0xffffffffu, st1, ac & 31);
            float  cs = (ac < 32) ? a0 : a1;
            float4 pc = s_pr[ac];
            if (lane == 0) out[t] = fmaf(pc.w - pc.z, cs, pc.z);
        }

        // publish final compact state for the expansion phase
        s_state[lane] = st0;
        if (lane < NKC - 32) s_state[lane + 32] = st1;
    }
    __syncthreads();

    // --- expand final state to (1, NOBS): 16 float4 stores/thread ---
    if (do_state) {
        float4*       o  = (float4*)(state_out + (size_t)b * NOBS);
        const uchar4* a4 = (const uchar4*)s_assign;
        #pragma unroll
        for (int i = 0; i < 16; i++) {
            uchar4 a = a4[tid + 128 * i];
            o[tid + 128 * i] =
                make_float4(s_state[a.x], s_state[a.y], s_state[a.z], s_state[a.w]);
        }
    }
}

// ============================================================
extern "C" void kernel_launch(void* const* d_in, const int* in_sizes, int n_in,
                              void* d_out, int out_size) {
    const int*    prev_kc   = (const int*)   d_in[0];
    const int*    curr_kc   = (const int*)   d_in[1];
    const float*  prev_corr = (const float*) d_in[2];
    const float*  kc_logits = (const float*) d_in[3];
    const float4* A4        = (const float4*)d_in[4];
    float*        out       = (float*)d_out;

    k1_prep<<<(NOBS * NKC / 8) / 256, 256>>>(A4);

    // Output layout: [probs (256*50) | state (256*8192)] concatenated.
    float* probs_out = out;
    float* state_out = out + BATCH * TLEN;
    int    do_state  = 1;

    if (out_size == BATCH * TLEN) {
        do_state  = 0;
        state_out = out;                 // unused
    } else if (out_size == BATCH * NOBS) {
        void* scratch = nullptr;
        cudaGetSymbolAddress(&scratch, g_probs_scratch);
        probs_out = (float*)scratch;
        state_out = out;
    }

    k2_fused<<<BATCH, 128>>>(prev_kc, curr_kc, prev_corr, kc_logits,
                             probs_out, state_out, do_state);
}